// round 8
// baseline (speedup 1.0000x reference)
#include <cuda_runtime.h>
#include <cuda_fp16.h>
#include <cstdint>

#define Bc  4
#define Nc  2048
#define INC 128
#define Hc  4
#define Dc  64
#define BHc (Bc*Hc)
#define NW  (Nc/32)

// ---- scratch ----
__device__ __half   g_hH[BHc*Nc*Dc];   // h fp16 [bh][n][d]
__device__ __half   g_E1h[BHc*Nc];     // exp(v)
__device__ __half   g_E2h[BHc*Nc];     // exp(0.2 v)
__device__ __half   g_F1h[BHc*Nc];     // exp(u)
__device__ __half   g_F2h[BHc*Nc];     // exp(0.2 u)
__device__ unsigned g_maskT[NW*Nc];    // [jword][i]

__device__ __forceinline__ uint32_t smem_u32(const void* p) {
    uint32_t a;
    asm("{ .reg .u64 t; cvta.to.shared.u64 t, %1; cvt.u32.u64 %0, t; }" : "=r"(a) : "l"(p));
    return a;
}
__device__ __forceinline__ uint32_t h2u(__half2 h) { return *(uint32_t*)&h; }

#define CP16(dst, src) asm volatile("cp.async.cg.shared.global [%0], [%1], 16;" :: "r"(dst), "l"(src))
#define CPCOMMIT()     asm volatile("cp.async.commit_group;" ::: "memory")
#define CPWAIT(n)      asm volatile("cp.async.wait_group %0;" :: "n"(n) : "memory")

// ---- pack adj -> transposed bitmask: 1 row/warp, uint4 loads (256B/lane in flight) ----
__global__ void __launch_bounds__(128) k_pack(const int* __restrict__ adj) {
    __shared__ unsigned char nib[4][2048];
    int w = threadIdx.x >> 5, lane = threadIdx.x & 31;
    int i = blockIdx.x * 4 + w;                        // row (grid 512 x 4 warps)
    const uint4* p = (const uint4*)(adj + (size_t)i * Nc);
    unsigned char* nb = nib[w];
#pragma unroll
    for (int k = 0; k < 16; k++) {
        uint4 v = p[lane + 32 * k];
        unsigned n = ((int)v.x > 0 ? 1u : 0u) | ((int)v.y > 0 ? 2u : 0u)
                   | ((int)v.z > 0 ? 4u : 0u) | ((int)v.w > 0 ? 8u : 0u);
        nb[lane + 32 * k] = (unsigned char)n;          // nibble for j-quad (lane+32k)
    }
    __syncwarp();
#pragma unroll
    for (int q = 0; q < 2; q++) {
        int jw = lane + q * 32;                        // word index within row (0..63)
        uint2 x = *(const uint2*)&nb[jw * 8];          // 8 quads -> 8 nibbles
        unsigned a = (x.x | (x.x >> 4)) & 0x00FF00FFu;
        a = (a | (a >> 8)) & 0x0000FFFFu;              // nib0..3 -> bits 0..15
        unsigned b = (x.y | (x.y >> 4)) & 0x00FF00FFu;
        b = (b | (b >> 8)) & 0x0000FFFFu;              // nib4..7 -> bits 0..15
        g_maskT[(size_t)jw * Nc + i] = a | (b << 16);
    }
}

// ---- HMMA linear (fp32 inputs converted in staging) with fused u/v/exp epilogue ----
__global__ void __launch_bounds__(128) k_lin_h(const float* __restrict__ x,
                                               const float* __restrict__ W,
                                               const float* __restrict__ att_src,
                                               const float* __restrict__ att_dst) {
    __shared__ __align__(16) char sX[64 * 256];
    __shared__ __align__(16) char sW[128 * 256];
    int tid = threadIdx.x, w = tid >> 5, lane = tid & 31;
    int g = lane >> 2, t = lane & 3;
    int n0 = blockIdx.x * 64, cgrp = blockIdx.y, b = blockIdx.z;

    const float4* xs = (const float4*)(x + ((size_t)b * Nc + n0) * INC);
#pragma unroll
    for (int q = 0; q < 16; q++) {
        int idx = tid + q * 128;
        int row = idx >> 5, u8 = idx & 31;
        float4 v = xs[idx];
        uint2 pk;
        __half2 p0 = __floats2half2_rn(v.x, v.y), p1 = __floats2half2_rn(v.z, v.w);
        pk.x = h2u(p0); pk.y = h2u(p1);
        *(uint2*)&sX[row * 256 + ((((u8 >> 1) * 16) ^ ((row & 7) * 16)) + (u8 & 1) * 8)] = pk;
    }
    const float4* ws = (const float4*)(W + (size_t)cgrp * 128 * INC);
#pragma unroll
    for (int q = 0; q < 32; q++) {
        int idx = tid + q * 128;
        int row = idx >> 5, u8 = idx & 31;
        float4 v = ws[idx];
        uint2 pk;
        __half2 p0 = __floats2half2_rn(v.x, v.y), p1 = __floats2half2_rn(v.z, v.w);
        pk.x = h2u(p0); pk.y = h2u(p1);
        *(uint2*)&sW[row * 256 + ((((u8 >> 1) * 16) ^ ((row & 7) * 16)) + (u8 & 1) * 8)] = pk;
    }
    __syncthreads();

    float c[16][4];
#pragma unroll
    for (int n = 0; n < 16; n++)
#pragma unroll
        for (int q = 0; q < 4; q++) c[n][q] = 0.f;

    uint32_t sXb = smem_u32(sX), sWb = smem_u32(sW);
    int arow = w * 16 + (lane & 15);
    uint32_t abase = sXb + (uint32_t)arow * 256;
    uint32_t hi16  = (uint32_t)(lane >> 4) * 16;
    uint32_t aswz  = (uint32_t)((arow & 7) * 16);
    int brow_base = (lane & 7) + ((lane >> 4) << 3);
    uint32_t bk16 = (uint32_t)(((lane >> 3) & 1) * 16);

#pragma unroll
    for (int ks = 0; ks < 8; ks++) {
        uint32_t a0, a1, a2, a3;
        uint32_t aaddr = abase + (((uint32_t)(ks * 32) + hi16) ^ aswz);
        asm volatile("ldmatrix.sync.aligned.m8n8.x4.shared.b16 {%0,%1,%2,%3}, [%4];"
                     : "=r"(a0), "=r"(a1), "=r"(a2), "=r"(a3) : "r"(aaddr));
#pragma unroll
        for (int p = 0; p < 8; p++) {
            int brow = p * 16 + brow_base;
            uint32_t baddr = sWb + (uint32_t)brow * 256 +
                             (((uint32_t)(ks * 32) + bk16) ^ ((uint32_t)((brow & 7) * 16)));
            uint32_t b0, b1, b2, b3;
            asm volatile("ldmatrix.sync.aligned.m8n8.x4.shared.b16 {%0,%1,%2,%3}, [%4];"
                         : "=r"(b0), "=r"(b1), "=r"(b2), "=r"(b3) : "r"(baddr));
            asm volatile("mma.sync.aligned.m16n8k16.row.col.f32.f16.f16.f32 "
                         "{%0,%1,%2,%3}, {%4,%5,%6,%7}, {%8,%9}, {%0,%1,%2,%3};"
                         : "+f"(c[2*p][0]), "+f"(c[2*p][1]), "+f"(c[2*p][2]), "+f"(c[2*p][3])
                         : "r"(a0), "r"(a1), "r"(a2), "r"(a3), "r"(b0), "r"(b1));
            asm volatile("mma.sync.aligned.m16n8k16.row.col.f32.f16.f16.f32 "
                         "{%0,%1,%2,%3}, {%4,%5,%6,%7}, {%8,%9}, {%0,%1,%2,%3};"
                         : "+f"(c[2*p+1][0]), "+f"(c[2*p+1][1]), "+f"(c[2*p+1][2]), "+f"(c[2*p+1][3])
                         : "r"(a0), "r"(a1), "r"(a2), "r"(a3), "r"(b2), "r"(b3));
        }
    }

    float up[2][2] = {{0.f,0.f},{0.f,0.f}}, vp[2][2] = {{0.f,0.f},{0.f,0.f}};
    int row0 = w * 16 + g;
#pragma unroll
    for (int n = 0; n < 16; n++) {
        int hl = n >> 3;
        int head = cgrp * 2 + hl;
        int d = (n & 7) * 8 + 2 * t;
        float2 as2 = __ldg((const float2*)(att_src + head * 64 + d));
        float2 ad2 = __ldg((const float2*)(att_dst + head * 64 + d));
        up[0][hl] += c[n][0]*as2.x + c[n][1]*as2.y;
        vp[0][hl] += c[n][0]*ad2.x + c[n][1]*ad2.y;
        up[1][hl] += c[n][2]*as2.x + c[n][3]*as2.y;
        vp[1][hl] += c[n][2]*ad2.x + c[n][3]*ad2.y;
        __half2 h0 = __floats2half2_rn(c[n][0], c[n][1]);
        __half2 h1 = __floats2half2_rn(c[n][2], c[n][3]);
        size_t base = ((size_t)(b * Hc + head) * Nc + n0 + row0) * Dc + d;
        *(uint32_t*)&g_hH[base]          = h2u(h0);
        *(uint32_t*)&g_hH[base + 8 * Dc] = h2u(h1);
    }
#pragma unroll
    for (int rh = 0; rh < 2; rh++)
#pragma unroll
        for (int hl = 0; hl < 2; hl++) {
            up[rh][hl] += __shfl_xor_sync(0xffffffffu, up[rh][hl], 1);
            up[rh][hl] += __shfl_xor_sync(0xffffffffu, up[rh][hl], 2);
            vp[rh][hl] += __shfl_xor_sync(0xffffffffu, vp[rh][hl], 1);
            vp[rh][hl] += __shfl_xor_sync(0xffffffffu, vp[rh][hl], 2);
        }
    if (t == 0) {
#pragma unroll
        for (int rh = 0; rh < 2; rh++)
#pragma unroll
            for (int hl = 0; hl < 2; hl++) {
                int head = cgrp * 2 + hl;
                int idx = (b * Hc + head) * Nc + n0 + row0 + rh * 8;
                float u = up[rh][hl], v = vp[rh][hl];
                g_F1h[idx] = __float2half_rn(expf(u));
                g_F2h[idx] = __float2half_rn(expf(0.2f * u));
                g_E1h[idx] = __float2half_rn(expf(v));
                g_E2h[idx] = __float2half_rn(expf(0.2f * v));
            }
    }
}

// ---- flash-GAT: 4 warps x (32 rows x 64 d), cp.async double buffer ----
__global__ void __launch_bounds__(128, 4) k_attn(float* __restrict__ out) {
    __shared__ __align__(16) char sH[2][16384];     // h tile fp16 [j][d], swizzled
    __shared__ __align__(16) unsigned smk[2][512];  // [buf][q*128 + i-row]
    __shared__ __align__(16) __half sE1[2][128], sE2[2][128];

    int tid = threadIdx.x;
    int w = tid >> 5, lane = tid & 31;
    int g = lane >> 2, t = lane & 3;
    int bh = blockIdx.y;
    int i0 = blockIdx.x * 128;
    const int eb = bh * Nc;
    const uint32_t sHb  = smem_u32(sH);
    const uint32_t smkb = smem_u32(smk);
    const uint32_t sE1b = smem_u32(sE1);
    const uint32_t sE2b = smem_u32(sE2);
    int rw = i0 + w * 32 + g;

    __half2 F1[4], F2[4];
#pragma unroll
    for (int r = 0; r < 4; r++) {
        F1[r] = __half2half2(g_F1h[eb + rw + r * 8]);
        F2[r] = __half2half2(g_F2h[eb + rw + r * 8]);
    }

    float c[2][8][4];
#pragma unroll
    for (int tl = 0; tl < 2; tl++)
#pragma unroll
        for (int n = 0; n < 8; n++)
#pragma unroll
            for (int q = 0; q < 4; q++) c[tl][n][q] = 0.f;
    float cz[2][4] = {{0.f,0.f,0.f,0.f},{0.f,0.f,0.f,0.f}};

    const char* hbase = (const char*)(g_hH + (size_t)eb * Dc);
    const uint32_t ONES = 0x3C003C00u;
    int tb = 2 * t;

    auto prefetch = [&](int ch, int buf) {
        int j0 = ch * 128;
#pragma unroll
        for (int q = 0; q < 8; q++) {
            int idx = tid + q * 128;
            int row = idx >> 3, cc = idx & 7;
            uint32_t dst = sHb + (uint32_t)buf * 16384 + (uint32_t)row * 128 +
                           (((uint32_t)cc * 16) ^ ((uint32_t)(row & 7) * 16));
            CP16(dst, hbase + ((size_t)(j0 + row) * 128 + cc * 16));
        }
        {
            int q = tid >> 5, off = (tid & 31) * 4;
            uint32_t dst = smkb + (uint32_t)buf * 2048 + (uint32_t)(q * 128 + off) * 4;
            CP16(dst, (const char*)(g_maskT + (size_t)(ch * 4 + q) * Nc + i0 + off));
        }
        if (tid < 16) {
            CP16(sE1b + (uint32_t)buf * 256 + tid * 16, (const char*)(g_E1h + eb + j0) + tid * 16);
        } else if (tid < 32) {
            CP16(sE2b + (uint32_t)buf * 256 + (tid - 16) * 16, (const char*)(g_E2h + eb + j0) + (tid - 16) * 16);
        }
        CPCOMMIT();
    };

    prefetch(0, 0);

    for (int ch = 0; ch < 16; ch++) {
        int buf = ch & 1;
        if (ch < 15) { prefetch(ch + 1, buf ^ 1); CPWAIT(1); }
        else         { CPWAIT(0); }
        __syncthreads();

        const __half2* e1p = (const __half2*)sE1[buf];
        const __half2* e2p = (const __half2*)sE2[buf];
        const unsigned* mk = smk[buf];
        uint32_t sHbuf = sHb + (uint32_t)buf * 16384;
        unsigned mw[4];

#pragma unroll
        for (int s = 0; s < 8; s++) {
            if (!(s & 1)) {
#pragma unroll
                for (int r = 0; r < 4; r++) mw[r] = mk[(s >> 1) * 128 + w * 32 + g + r * 8];
            }
            __half2 e1lo = e1p[s * 8 + t],     e1hi = e1p[s * 8 + 4 + t];
            __half2 e2lo = e2p[s * 8 + t],     e2hi = e2p[s * 8 + 4 + t];

            uint32_t afr[2][4];
#pragma unroll
            for (int r = 0; r < 4; r++) {
                unsigned m = mw[r] >> ((s & 1) * 16);
                uint32_t wl = h2u(__hmax2(__hmul2(F1[r], e1lo), __hmul2(F2[r], e2lo)));
                uint32_t wh = h2u(__hmax2(__hmul2(F1[r], e1hi), __hmul2(F2[r], e2hi)));
                uint32_t bl = (m >> tb) & 3u, bhb = (m >> (tb + 8)) & 3u;
                wl &= ((bl & 1u) * 0xFFFFu) | ((bl >> 1) * 0xFFFF0000u);
                wh &= ((bhb & 1u) * 0xFFFFu) | ((bhb >> 1) * 0xFFFF0000u);
                afr[r >> 1][(r & 1)]     = wl;
                afr[r >> 1][2 + (r & 1)] = wh;
            }

#pragma unroll
            for (int tl = 0; tl < 2; tl++)
                asm volatile("mma.sync.aligned.m16n8k16.row.col.f32.f16.f16.f32 "
                             "{%0,%1,%2,%3}, {%4,%5,%6,%7}, {%8,%9}, {%0,%1,%2,%3};"
                             : "+f"(cz[tl][0]), "+f"(cz[tl][1]), "+f"(cz[tl][2]), "+f"(cz[tl][3])
                             : "r"(afr[tl][0]), "r"(afr[tl][1]), "r"(afr[tl][2]), "r"(afr[tl][3]),
                               "r"(ONES), "r"(ONES));

            int mrow = s * 16 + (lane & 15);
            uint32_t rbase = sHbuf + (uint32_t)mrow * 128;
            uint32_t swz = (uint32_t)((mrow & 7) * 16);
            uint32_t hi  = (uint32_t)((lane >> 4) * 16);
#pragma unroll
            for (int p = 0; p < 4; p++) {
                uint32_t addr = rbase + (((uint32_t)(p * 32) + hi) ^ swz);
                uint32_t b0, b1, b2, b3;
                asm volatile("ldmatrix.sync.aligned.m8n8.x4.trans.shared.b16 {%0,%1,%2,%3}, [%4];"
                             : "=r"(b0), "=r"(b1), "=r"(b2), "=r"(b3) : "r"(addr));
#pragma unroll
                for (int tl = 0; tl < 2; tl++) {
                    asm volatile("mma.sync.aligned.m16n8k16.row.col.f32.f16.f16.f32 "
                                 "{%0,%1,%2,%3}, {%4,%5,%6,%7}, {%8,%9}, {%0,%1,%2,%3};"
                                 : "+f"(c[tl][2*p][0]), "+f"(c[tl][2*p][1]), "+f"(c[tl][2*p][2]), "+f"(c[tl][2*p][3])
                                 : "r"(afr[tl][0]), "r"(afr[tl][1]), "r"(afr[tl][2]), "r"(afr[tl][3]),
                                   "r"(b0), "r"(b1));
                    asm volatile("mma.sync.aligned.m16n8k16.row.col.f32.f16.f16.f32 "
                                 "{%0,%1,%2,%3}, {%4,%5,%6,%7}, {%8,%9}, {%0,%1,%2,%3};"
                                 : "+f"(c[tl][2*p+1][0]), "+f"(c[tl][2*p+1][1]), "+f"(c[tl][2*p+1][2]), "+f"(c[tl][2*p+1][3])
                                 : "r"(afr[tl][0]), "r"(afr[tl][1]), "r"(afr[tl][2]), "r"(afr[tl][3]),
                                   "r"(b2), "r"(b3));
                }
            }
        }
        __syncthreads();
    }

    int b = bh >> 2, hd = bh & 3;
#pragma unroll
    for (int tl = 0; tl < 2; tl++) {
        float inv0 = 1.f / cz[tl][0];
        float inv1 = 1.f / cz[tl][2];
        int row0 = i0 + w * 32 + g + tl * 16;
        float* d0 = out + ((size_t)(b * Nc) + row0) * (Hc * Dc) + hd * Dc + 2 * t;
        float* d1 = d0 + 8 * (Hc * Dc);
#pragma unroll
        for (int n = 0; n < 8; n++) {
            *(float2*)(d0 + n * 8) = make_float2(c[tl][n][0] * inv0, c[tl][n][1] * inv0);
            *(float2*)(d1 + n * 8) = make_float2(c[tl][n][2] * inv1, c[tl][n][3] * inv1);
        }
    }
}

extern "C" void kernel_launch(void* const* d_in, const int* in_sizes, int n_in,
                              void* d_out, int out_size) {
    const float* x       = (const float*)d_in[0];
    const int*   adj     = (const int*)  d_in[1];
    const float* W       = (const float*)d_in[2];
    const float* att_src = (const float*)d_in[3];
    const float* att_dst = (const float*)d_in[4];
    float* out = (float*)d_out;

    k_pack<<<512, 128>>>(adj);
    k_lin_h<<<dim3(Nc / 64, 2, Bc), 128>>>(x, W, att_src, att_dst);
    k_attn<<<dim3(Nc / 128, BHc), 128>>>(out);
}

// round 9
// speedup vs baseline: 1.0711x; 1.0711x over previous
#include <cuda_runtime.h>
#include <cuda_fp16.h>
#include <cstdint>

#define Bc  4
#define Nc  2048
#define INC 128
#define Hc  4
#define Dc  64
#define BHc (Bc*Hc)
#define NW  (Nc/32)

// ---- scratch ----
__device__ __half   g_hH[BHc*Nc*Dc];   // h fp16 [bh][n][d]
__device__ __half   g_E1h[BHc*Nc];     // exp(v)
__device__ __half   g_E2h[BHc*Nc];     // exp(0.2 v)
__device__ __half   g_F1h[BHc*Nc];     // exp(u)
__device__ __half   g_F2h[BHc*Nc];     // exp(0.2 u)
__device__ unsigned g_maskT[NW*Nc];    // [jword][i]

__device__ __forceinline__ uint32_t smem_u32(const void* p) {
    uint32_t a;
    asm("{ .reg .u64 t; cvta.to.shared.u64 t, %1; cvt.u32.u64 %0, t; }" : "=r"(a) : "l"(p));
    return a;
}
__device__ __forceinline__ uint32_t h2u(__half2 h) { return *(uint32_t*)&h; }
__device__ __forceinline__ uint32_t bfe_s(uint32_t m, int pos) {
    int r;
    asm("bfe.s32 %0, %1, %2, 1;" : "=r"(r) : "r"((int)m), "r"(pos));
    return (uint32_t)r;
}

#define CP16(dst, src) asm volatile("cp.async.cg.shared.global [%0], [%1], 16;" :: "r"(dst), "l"(src))
#define CPCOMMIT()     asm volatile("cp.async.commit_group;" ::: "memory")
#define CPWAIT(n)      asm volatile("cp.async.wait_group %0;" :: "n"(n) : "memory")

// ---- pack adj -> transposed bitmask, 16 words per warp (round-7 version) ----
__global__ void __launch_bounds__(256) k_pack(const int* __restrict__ adj) {
    int task = blockIdx.x * 8 + (threadIdx.x >> 5);   // 8192 warp-tasks
    int lane = threadIdx.x & 31;
    int i  = task & (Nc - 1);
    int jc = task >> 11;
    const int* p = adj + (size_t)i * Nc + jc * 512 + lane;
    int v[16];
#pragma unroll
    for (int k = 0; k < 16; k++) v[k] = p[32 * k];
    unsigned bal[16];
#pragma unroll
    for (int k = 0; k < 16; k++) bal[k] = __ballot_sync(0xffffffffu, v[k] > 0);
    if (lane < 16)
        g_maskT[(size_t)(jc * 16 + lane) * Nc + i] = bal[lane];
}

// ---- HMMA linear (fp32 inputs converted in staging) with fused u/v/exp epilogue ----
__global__ void __launch_bounds__(128) k_lin_h(const float* __restrict__ x,
                                               const float* __restrict__ W,
                                               const float* __restrict__ att_src,
                                               const float* __restrict__ att_dst) {
    __shared__ __align__(16) char sX[64 * 256];
    __shared__ __align__(16) char sW[128 * 256];
    int tid = threadIdx.x, w = tid >> 5, lane = tid & 31;
    int g = lane >> 2, t = lane & 3;
    int n0 = blockIdx.x * 64, cgrp = blockIdx.y, b = blockIdx.z;

    const float4* xs = (const float4*)(x + ((size_t)b * Nc + n0) * INC);
#pragma unroll
    for (int q = 0; q < 16; q++) {
        int idx = tid + q * 128;
        int row = idx >> 5, u8 = idx & 31;
        float4 v = xs[idx];
        uint2 pk;
        __half2 p0 = __floats2half2_rn(v.x, v.y), p1 = __floats2half2_rn(v.z, v.w);
        pk.x = h2u(p0); pk.y = h2u(p1);
        *(uint2*)&sX[row * 256 + ((((u8 >> 1) * 16) ^ ((row & 7) * 16)) + (u8 & 1) * 8)] = pk;
    }
    const float4* ws = (const float4*)(W + (size_t)cgrp * 128 * INC);
#pragma unroll
    for (int q = 0; q < 32; q++) {
        int idx = tid + q * 128;
        int row = idx >> 5, u8 = idx & 31;
        float4 v = ws[idx];
        uint2 pk;
        __half2 p0 = __floats2half2_rn(v.x, v.y), p1 = __floats2half2_rn(v.z, v.w);
        pk.x = h2u(p0); pk.y = h2u(p1);
        *(uint2*)&sW[row * 256 + ((((u8 >> 1) * 16) ^ ((row & 7) * 16)) + (u8 & 1) * 8)] = pk;
    }
    __syncthreads();

    float c[16][4];
#pragma unroll
    for (int n = 0; n < 16; n++)
#pragma unroll
        for (int q = 0; q < 4; q++) c[n][q] = 0.f;

    uint32_t sXb = smem_u32(sX), sWb = smem_u32(sW);
    int arow = w * 16 + (lane & 15);
    uint32_t abase = sXb + (uint32_t)arow * 256;
    uint32_t hi16  = (uint32_t)(lane >> 4) * 16;
    uint32_t aswz  = (uint32_t)((arow & 7) * 16);
    int brow_base = (lane & 7) + ((lane >> 4) << 3);
    uint32_t bk16 = (uint32_t)(((lane >> 3) & 1) * 16);

#pragma unroll
    for (int ks = 0; ks < 8; ks++) {
        uint32_t a0, a1, a2, a3;
        uint32_t aaddr = abase + (((uint32_t)(ks * 32) + hi16) ^ aswz);
        asm volatile("ldmatrix.sync.aligned.m8n8.x4.shared.b16 {%0,%1,%2,%3}, [%4];"
                     : "=r"(a0), "=r"(a1), "=r"(a2), "=r"(a3) : "r"(aaddr));
#pragma unroll
        for (int p = 0; p < 8; p++) {
            int brow = p * 16 + brow_base;
            uint32_t baddr = sWb + (uint32_t)brow * 256 +
                             (((uint32_t)(ks * 32) + bk16) ^ ((uint32_t)((brow & 7) * 16)));
            uint32_t b0, b1, b2, b3;
            asm volatile("ldmatrix.sync.aligned.m8n8.x4.shared.b16 {%0,%1,%2,%3}, [%4];"
                         : "=r"(b0), "=r"(b1), "=r"(b2), "=r"(b3) : "r"(baddr));
            asm volatile("mma.sync.aligned.m16n8k16.row.col.f32.f16.f16.f32 "
                         "{%0,%1,%2,%3}, {%4,%5,%6,%7}, {%8,%9}, {%0,%1,%2,%3};"
                         : "+f"(c[2*p][0]), "+f"(c[2*p][1]), "+f"(c[2*p][2]), "+f"(c[2*p][3])
                         : "r"(a0), "r"(a1), "r"(a2), "r"(a3), "r"(b0), "r"(b1));
            asm volatile("mma.sync.aligned.m16n8k16.row.col.f32.f16.f16.f32 "
                         "{%0,%1,%2,%3}, {%4,%5,%6,%7}, {%8,%9}, {%0,%1,%2,%3};"
                         : "+f"(c[2*p+1][0]), "+f"(c[2*p+1][1]), "+f"(c[2*p+1][2]), "+f"(c[2*p+1][3])
                         : "r"(a0), "r"(a1), "r"(a2), "r"(a3), "r"(b2), "r"(b3));
        }
    }

    float up[2][2] = {{0.f,0.f},{0.f,0.f}}, vp[2][2] = {{0.f,0.f},{0.f,0.f}};
    int row0 = w * 16 + g;
#pragma unroll
    for (int n = 0; n < 16; n++) {
        int hl = n >> 3;
        int head = cgrp * 2 + hl;
        int d = (n & 7) * 8 + 2 * t;
        float2 as2 = __ldg((const float2*)(att_src + head * 64 + d));
        float2 ad2 = __ldg((const float2*)(att_dst + head * 64 + d));
        up[0][hl] += c[n][0]*as2.x + c[n][1]*as2.y;
        vp[0][hl] += c[n][0]*ad2.x + c[n][1]*ad2.y;
        up[1][hl] += c[n][2]*as2.x + c[n][3]*as2.y;
        vp[1][hl] += c[n][2]*ad2.x + c[n][3]*ad2.y;
        __half2 h0 = __floats2half2_rn(c[n][0], c[n][1]);
        __half2 h1 = __floats2half2_rn(c[n][2], c[n][3]);
        size_t base = ((size_t)(b * Hc + head) * Nc + n0 + row0) * Dc + d;
        *(uint32_t*)&g_hH[base]          = h2u(h0);
        *(uint32_t*)&g_hH[base + 8 * Dc] = h2u(h1);
    }
#pragma unroll
    for (int rh = 0; rh < 2; rh++)
#pragma unroll
        for (int hl = 0; hl < 2; hl++) {
            up[rh][hl] += __shfl_xor_sync(0xffffffffu, up[rh][hl], 1);
            up[rh][hl] += __shfl_xor_sync(0xffffffffu, up[rh][hl], 2);
            vp[rh][hl] += __shfl_xor_sync(0xffffffffu, vp[rh][hl], 1);
            vp[rh][hl] += __shfl_xor_sync(0xffffffffu, vp[rh][hl], 2);
        }
    if (t == 0) {
#pragma unroll
        for (int rh = 0; rh < 2; rh++)
#pragma unroll
            for (int hl = 0; hl < 2; hl++) {
                int head = cgrp * 2 + hl;
                int idx = (b * Hc + head) * Nc + n0 + row0 + rh * 8;
                float u = up[rh][hl], v = vp[rh][hl];
                g_F1h[idx] = __float2half_rn(expf(u));
                g_F2h[idx] = __float2half_rn(expf(0.2f * u));
                g_E1h[idx] = __float2half_rn(expf(v));
                g_E2h[idx] = __float2half_rn(expf(0.2f * v));
            }
    }
}

// ---- flash-GAT: 64-row i-tiles (512 CTAs), warp=16 rows, reg-pipelined B frags ----
__global__ void __launch_bounds__(128, 4) k_attn(float* __restrict__ out) {
    __shared__ __align__(16) char sH[2][16384];     // h tile fp16 [j][d], swizzled
    __shared__ __align__(16) unsigned smk[2][256];  // [buf][jw*64 + row]
    __shared__ __align__(16) __half sE1[2][128], sE2[2][128];

    int tid = threadIdx.x;
    int w = tid >> 5, lane = tid & 31;
    int g = lane >> 2, t = lane & 3;
    int bh = blockIdx.y;
    int i0 = blockIdx.x * 64;
    const int eb = bh * Nc;
    const uint32_t sHb  = smem_u32(sH);
    const uint32_t smkb = smem_u32(smk);
    const uint32_t sE1b = smem_u32(sE1);
    const uint32_t sE2b = smem_u32(sE2);
    int r0 = w * 16 + g;           // local rows r0, r0+8

    __half2 F1a = __half2half2(g_F1h[eb + i0 + r0]);
    __half2 F2a = __half2half2(g_F2h[eb + i0 + r0]);
    __half2 F1b = __half2half2(g_F1h[eb + i0 + r0 + 8]);
    __half2 F2b = __half2half2(g_F2h[eb + i0 + r0 + 8]);

    float c[8][4];
#pragma unroll
    for (int n = 0; n < 8; n++)
#pragma unroll
        for (int q = 0; q < 4; q++) c[n][q] = 0.f;
    float cz[4] = {0.f, 0.f, 0.f, 0.f};

    const char* hbase = (const char*)(g_hH + (size_t)eb * Dc);
    const uint32_t ONES = 0x3C003C00u;
    int tb = 2 * t;

    auto prefetch = [&](int ch, int buf) {
        int j0 = ch * 128;
#pragma unroll
        for (int q = 0; q < 8; q++) {
            int idx = tid + q * 128;
            int row = idx >> 3, cc = idx & 7;
            uint32_t dst = sHb + (uint32_t)buf * 16384 + (uint32_t)row * 128 +
                           (((uint32_t)cc * 16) ^ ((uint32_t)(row & 7) * 16));
            CP16(dst, hbase + ((size_t)(j0 + row) * 128 + cc * 16));
        }
        if (tid < 64) {
            int jw = tid >> 4, rb = (tid & 15) * 4;
            uint32_t dst = smkb + (uint32_t)buf * 1024 + (uint32_t)(jw * 64 + rb) * 4;
            CP16(dst, (const char*)(g_maskT + (size_t)(ch * 4 + jw) * Nc + i0 + rb));
        } else if (tid < 80) {
            CP16(sE1b + (uint32_t)buf * 256 + (tid - 64) * 16, (const char*)(g_E1h + eb + j0) + (tid - 64) * 16);
        } else if (tid < 96) {
            CP16(sE2b + (uint32_t)buf * 256 + (tid - 80) * 16, (const char*)(g_E2h + eb + j0) + (tid - 80) * 16);
        }
        CPCOMMIT();
    };

    prefetch(0, 0);

    uint32_t lmbase_row = (uint32_t)(lane & 15);
    uint32_t lmhi = (uint32_t)((lane >> 4) * 16);

    for (int ch = 0; ch < 16; ch++) {
        int buf = ch & 1;
        if (ch < 15) { prefetch(ch + 1, buf ^ 1); CPWAIT(1); }
        else         { CPWAIT(0); }
        __syncthreads();

        const __half2* e1p = (const __half2*)sE1[buf];
        const __half2* e2p = (const __half2*)sE2[buf];
        const unsigned* mk = smk[buf];
        uint32_t sHbuf = sHb + (uint32_t)buf * 16384;

        uint32_t bfr[2][16];
        // preload B for s=0
        {
            uint32_t mrow = lmbase_row;
            uint32_t rbase = sHbuf + mrow * 128;
            uint32_t swz = (mrow & 7) * 16;
#pragma unroll
            for (int p = 0; p < 4; p++) {
                uint32_t addr = rbase + (((uint32_t)(p * 32) + lmhi) ^ swz);
                asm volatile("ldmatrix.sync.aligned.m8n8.x4.trans.shared.b16 {%0,%1,%2,%3}, [%4];"
                             : "=r"(bfr[0][p*4+0]), "=r"(bfr[0][p*4+1]),
                               "=r"(bfr[0][p*4+2]), "=r"(bfr[0][p*4+3]) : "r"(addr));
            }
        }

        unsigned mw0 = 0, mw1 = 0;
#pragma unroll
        for (int s = 0; s < 8; s++) {
            const int cur = s & 1;
            if (!(s & 1)) {
                mw0 = mk[(s >> 1) * 64 + r0];
                mw1 = mk[(s >> 1) * 64 + r0 + 8];
            }
            __half2 e1lo = e1p[s * 8 + t],     e1hi = e1p[s * 8 + 4 + t];
            __half2 e2lo = e2p[s * 8 + t],     e2hi = e2p[s * 8 + 4 + t];

            const int base = (s & 1) * 16 + tb;
            uint32_t a0, a1, a2, a3;
            {
                uint32_t wl = h2u(__hmax2(__hmul2(F1a, e1lo), __hmul2(F2a, e2lo)));
                uint32_t wh = h2u(__hmax2(__hmul2(F1a, e1hi), __hmul2(F2a, e2hi)));
                uint32_t mlo = __byte_perm(bfe_s(mw0, base),     bfe_s(mw0, base + 1), 0x5410);
                uint32_t mhi = __byte_perm(bfe_s(mw0, base + 8), bfe_s(mw0, base + 9), 0x5410);
                a0 = wl & mlo;  a2 = wh & mhi;
            }
            {
                uint32_t wl = h2u(__hmax2(__hmul2(F1b, e1lo), __hmul2(F2b, e2lo)));
                uint32_t wh = h2u(__hmax2(__hmul2(F1b, e1hi), __hmul2(F2b, e2hi)));
                uint32_t mlo = __byte_perm(bfe_s(mw1, base),     bfe_s(mw1, base + 1), 0x5410);
                uint32_t mhi = __byte_perm(bfe_s(mw1, base + 8), bfe_s(mw1, base + 9), 0x5410);
                a1 = wl & mlo;  a3 = wh & mhi;
            }

            // prefetch next step's B fragments (hide LDSM latency behind MMAs)
            if (s < 7) {
                uint32_t mrow = (uint32_t)((s + 1) * 16) + lmbase_row;
                uint32_t rbase = sHbuf + mrow * 128;
                uint32_t swz = (mrow & 7) * 16;
#pragma unroll
                for (int p = 0; p < 4; p++) {
                    uint32_t addr = rbase + (((uint32_t)(p * 32) + lmhi) ^ swz);
                    asm volatile("ldmatrix.sync.aligned.m8n8.x4.trans.shared.b16 {%0,%1,%2,%3}, [%4];"
                                 : "=r"(bfr[cur^1][p*4+0]), "=r"(bfr[cur^1][p*4+1]),
                                   "=r"(bfr[cur^1][p*4+2]), "=r"(bfr[cur^1][p*4+3]) : "r"(addr));
                }
            }

            asm volatile("mma.sync.aligned.m16n8k16.row.col.f32.f16.f16.f32 "
                         "{%0,%1,%2,%3}, {%4,%5,%6,%7}, {%8,%9}, {%0,%1,%2,%3};"
                         : "+f"(cz[0]), "+f"(cz[1]), "+f"(cz[2]), "+f"(cz[3])
                         : "r"(a0), "r"(a1), "r"(a2), "r"(a3), "r"(ONES), "r"(ONES));
#pragma unroll
            for (int p = 0; p < 4; p++) {
                asm volatile("mma.sync.aligned.m16n8k16.row.col.f32.f16.f16.f32 "
                             "{%0,%1,%2,%3}, {%4,%5,%6,%7}, {%8,%9}, {%0,%1,%2,%3};"
                             : "+f"(c[2*p][0]), "+f"(c[2*p][1]), "+f"(c[2*p][2]), "+f"(c[2*p][3])
                             : "r"(a0), "r"(a1), "r"(a2), "r"(a3),
                               "r"(bfr[cur][p*4+0]), "r"(bfr[cur][p*4+1]));
                asm volatile("mma.sync.aligned.m16n8k16.row.col.f32.f16.f16.f32 "
                             "{%0,%1,%2,%3}, {%4,%5,%6,%7}, {%8,%9}, {%0,%1,%2,%3};"
                             : "+f"(c[2*p+1][0]), "+f"(c[2*p+1][1]), "+f"(c[2*p+1][2]), "+f"(c[2*p+1][3])
                             : "r"(a0), "r"(a1), "r"(a2), "r"(a3),
                               "r"(bfr[cur][p*4+2]), "r"(bfr[cur][p*4+3]));
            }
        }
        __syncthreads();
    }

    float inv0 = 1.f / cz[0];
    float inv1 = 1.f / cz[2];

    int b = bh >> 2, hd = bh & 3;
    int grow = i0 + r0;
    float* d0 = out + ((size_t)(b * Nc) + grow) * (Hc * Dc) + hd * Dc + 2 * t;
    float* d1 = d0 + 8 * (Hc * Dc);
#pragma unroll
    for (int n = 0; n < 8; n++) {
        *(float2*)(d0 + n * 8) = make_float2(c[n][0] * inv0, c[n][1] * inv0);
        *(float2*)(d1 + n * 8) = make_float2(c[n][2] * inv1, c[n][3] * inv1);
    }
}

extern "C" void kernel_launch(void* const* d_in, const int* in_sizes, int n_in,
                              void* d_out, int out_size) {
    const float* x       = (const float*)d_in[0];
    const int*   adj     = (const int*)  d_in[1];
    const float* W       = (const float*)d_in[2];
    const float* att_src = (const float*)d_in[3];
    const float* att_dst = (const float*)d_in[4];
    float* out = (float*)d_out;

    k_pack<<<1024, 256>>>(adj);
    k_lin_h<<<dim3(Nc / 64, 2, Bc), 128>>>(x, W, att_src, att_dst);
    k_attn<<<dim3(Nc / 64, BHc), 128>>>(out);
}

// round 10
// speedup vs baseline: 1.1643x; 1.0870x over previous
#include <cuda_runtime.h>
#include <cuda_fp16.h>
#include <cstdint>

#define Bc  4
#define Nc  2048
#define INC 128
#define Hc  4
#define Dc  64
#define BHc (Bc*Hc)

// ---- scratch ----
__device__ __half   g_hH[BHc*Nc*Dc];   // h fp16 [bh][n][d]
__device__ __half   g_E1h[BHc*Nc];     // exp(v)
__device__ __half   g_E2h[BHc*Nc];     // exp(0.2 v)
__device__ __half   g_F1h[BHc*Nc];     // exp(u)
__device__ __half   g_F2h[BHc*Nc];     // exp(0.2 u)
__device__ __half   g_maskH[Nc*Nc];    // adj as fp16 {1.0, 0.0}, [i][j]

__device__ __forceinline__ uint32_t smem_u32(const void* p) {
    uint32_t a;
    asm("{ .reg .u64 t; cvta.to.shared.u64 t, %1; cvt.u32.u64 %0, t; }" : "=r"(a) : "l"(p));
    return a;
}
__device__ __forceinline__ uint32_t h2u(__half2 h) { return *(uint32_t*)&h; }

#define CP16(dst, src) asm volatile("cp.async.cg.shared.global [%0], [%1], 16;" :: "r"(dst), "l"(src))
#define CPCOMMIT()     asm volatile("cp.async.commit_group;" ::: "memory")
#define CPWAIT(n)      asm volatile("cp.async.wait_group %0;" :: "n"(n) : "memory")

// ---- adj int32 -> fp16 {1,0}, fully coalesced streaming convert ----
__global__ void __launch_bounds__(256) k_packh(const int* __restrict__ adj) {
    int task = blockIdx.x * 8 + (threadIdx.x >> 5);   // 8192 warp-tasks, 512 ints each
    int lane = threadIdx.x & 31;
    const uint4* p = (const uint4*)adj + (size_t)task * 128 + lane;
    uint2* o = (uint2*)(g_maskH + (size_t)task * 512) + lane;
    uint4 v0 = p[0], v1 = p[32], v2 = p[64], v3 = p[96];
#define CVT2(vv) make_uint2( \
        (((int)(vv).x > 0) ? 0x3C00u : 0u) | (((int)(vv).y > 0) ? 0x3C000000u : 0u), \
        (((int)(vv).z > 0) ? 0x3C00u : 0u) | (((int)(vv).w > 0) ? 0x3C000000u : 0u))
    o[0]  = CVT2(v0);
    o[32] = CVT2(v1);
    o[64] = CVT2(v2);
    o[96] = CVT2(v3);
#undef CVT2
}

// ---- HMMA linear (fp32 inputs converted in staging) with fused u/v/exp epilogue ----
__global__ void __launch_bounds__(128) k_lin_h(const float* __restrict__ x,
                                               const float* __restrict__ W,
                                               const float* __restrict__ att_src,
                                               const float* __restrict__ att_dst) {
    __shared__ __align__(16) char sX[64 * 256];
    __shared__ __align__(16) char sW[128 * 256];
    int tid = threadIdx.x, w = tid >> 5, lane = tid & 31;
    int g = lane >> 2, t = lane & 3;
    int n0 = blockIdx.x * 64, cgrp = blockIdx.y, b = blockIdx.z;

    const float4* xs = (const float4*)(x + ((size_t)b * Nc + n0) * INC);
#pragma unroll
    for (int q = 0; q < 16; q++) {
        int idx = tid + q * 128;
        int row = idx >> 5, u8 = idx & 31;
        float4 v = xs[idx];
        uint2 pk;
        __half2 p0 = __floats2half2_rn(v.x, v.y), p1 = __floats2half2_rn(v.z, v.w);
        pk.x = h2u(p0); pk.y = h2u(p1);
        *(uint2*)&sX[row * 256 + ((((u8 >> 1) * 16) ^ ((row & 7) * 16)) + (u8 & 1) * 8)] = pk;
    }
    const float4* ws = (const float4*)(W + (size_t)cgrp * 128 * INC);
#pragma unroll
    for (int q = 0; q < 32; q++) {
        int idx = tid + q * 128;
        int row = idx >> 5, u8 = idx & 31;
        float4 v = ws[idx];
        uint2 pk;
        __half2 p0 = __floats2half2_rn(v.x, v.y), p1 = __floats2half2_rn(v.z, v.w);
        pk.x = h2u(p0); pk.y = h2u(p1);
        *(uint2*)&sW[row * 256 + ((((u8 >> 1) * 16) ^ ((row & 7) * 16)) + (u8 & 1) * 8)] = pk;
    }
    __syncthreads();

    float c[16][4];
#pragma unroll
    for (int n = 0; n < 16; n++)
#pragma unroll
        for (int q = 0; q < 4; q++) c[n][q] = 0.f;

    uint32_t sXb = smem_u32(sX), sWb = smem_u32(sW);
    int arow = w * 16 + (lane & 15);
    uint32_t abase = sXb + (uint32_t)arow * 256;
    uint32_t hi16  = (uint32_t)(lane >> 4) * 16;
    uint32_t aswz  = (uint32_t)((arow & 7) * 16);
    int brow_base = (lane & 7) + ((lane >> 4) << 3);
    uint32_t bk16 = (uint32_t)(((lane >> 3) & 1) * 16);

#pragma unroll
    for (int ks = 0; ks < 8; ks++) {
        uint32_t a0, a1, a2, a3;
        uint32_t aaddr = abase + (((uint32_t)(ks * 32) + hi16) ^ aswz);
        asm volatile("ldmatrix.sync.aligned.m8n8.x4.shared.b16 {%0,%1,%2,%3}, [%4];"
                     : "=r"(a0), "=r"(a1), "=r"(a2), "=r"(a3) : "r"(aaddr));
#pragma unroll
        for (int p = 0; p < 8; p++) {
            int brow = p * 16 + brow_base;
            uint32_t baddr = sWb + (uint32_t)brow * 256 +
                             (((uint32_t)(ks * 32) + bk16) ^ ((uint32_t)((brow & 7) * 16)));
            uint32_t b0, b1, b2, b3;
            asm volatile("ldmatrix.sync.aligned.m8n8.x4.shared.b16 {%0,%1,%2,%3}, [%4];"
                         : "=r"(b0), "=r"(b1), "=r"(b2), "=r"(b3) : "r"(baddr));
            asm volatile("mma.sync.aligned.m16n8k16.row.col.f32.f16.f16.f32 "
                         "{%0,%1,%2,%3}, {%4,%5,%6,%7}, {%8,%9}, {%0,%1,%2,%3};"
                         : "+f"(c[2*p][0]), "+f"(c[2*p][1]), "+f"(c[2*p][2]), "+f"(c[2*p][3])
                         : "r"(a0), "r"(a1), "r"(a2), "r"(a3), "r"(b0), "r"(b1));
            asm volatile("mma.sync.aligned.m16n8k16.row.col.f32.f16.f16.f32 "
                         "{%0,%1,%2,%3}, {%4,%5,%6,%7}, {%8,%9}, {%0,%1,%2,%3};"
                         : "+f"(c[2*p+1][0]), "+f"(c[2*p+1][1]), "+f"(c[2*p+1][2]), "+f"(c[2*p+1][3])
                         : "r"(a0), "r"(a1), "r"(a2), "r"(a3), "r"(b2), "r"(b3));
        }
    }

    float up[2][2] = {{0.f,0.f},{0.f,0.f}}, vp[2][2] = {{0.f,0.f},{0.f,0.f}};
    int row0 = w * 16 + g;
#pragma unroll
    for (int n = 0; n < 16; n++) {
        int hl = n >> 3;
        int head = cgrp * 2 + hl;
        int d = (n & 7) * 8 + 2 * t;
        float2 as2 = __ldg((const float2*)(att_src + head * 64 + d));
        float2 ad2 = __ldg((const float2*)(att_dst + head * 64 + d));
        up[0][hl] += c[n][0]*as2.x + c[n][1]*as2.y;
        vp[0][hl] += c[n][0]*ad2.x + c[n][1]*ad2.y;
        up[1][hl] += c[n][2]*as2.x + c[n][3]*as2.y;
        vp[1][hl] += c[n][2]*ad2.x + c[n][3]*ad2.y;
        __half2 h0 = __floats2half2_rn(c[n][0], c[n][1]);
        __half2 h1 = __floats2half2_rn(c[n][2], c[n][3]);
        size_t base = ((size_t)(b * Hc + head) * Nc + n0 + row0) * Dc + d;
        *(uint32_t*)&g_hH[base]          = h2u(h0);
        *(uint32_t*)&g_hH[base + 8 * Dc] = h2u(h1);
    }
#pragma unroll
    for (int rh = 0; rh < 2; rh++)
#pragma unroll
        for (int hl = 0; hl < 2; hl++) {
            up[rh][hl] += __shfl_xor_sync(0xffffffffu, up[rh][hl], 1);
            up[rh][hl] += __shfl_xor_sync(0xffffffffu, up[rh][hl], 2);
            vp[rh][hl] += __shfl_xor_sync(0xffffffffu, vp[rh][hl], 1);
            vp[rh][hl] += __shfl_xor_sync(0xffffffffu, vp[rh][hl], 2);
        }
    if (t == 0) {
#pragma unroll
        for (int rh = 0; rh < 2; rh++)
#pragma unroll
            for (int hl = 0; hl < 2; hl++) {
                int head = cgrp * 2 + hl;
                int idx = (b * Hc + head) * Nc + n0 + row0 + rh * 8;
                float u = up[rh][hl], v = vp[rh][hl];
                g_F1h[idx] = __float2half_rn(expf(u));
                g_F2h[idx] = __float2half_rn(expf(0.2f * u));
                g_E1h[idx] = __float2half_rn(expf(v));
                g_E2h[idx] = __float2half_rn(expf(0.2f * v));
            }
    }
}

// smem layout (dynamic)
#define SH_OFF   0          // 2 x 16384: h tile fp16 [j][d]
#define SM_OFF   32768      // 2 x 16384: mask tile fp16 [i-row][j]
#define SE1_OFF  65536      // 2 x 256
#define SE2_OFF  66048      // 2 x 256
#define SMEM_ATTN 66560

// ---- flash-GAT: mask via ldmatrix fp16 fragment, reg-pipelined B frags ----
__global__ void __launch_bounds__(128, 3) k_attn(float* __restrict__ out) {
    extern __shared__ __align__(16) char smem[];
    int tid = threadIdx.x;
    int w = tid >> 5, lane = tid & 31;
    int g = lane >> 2, t = lane & 3;
    int bh = blockIdx.y;
    int i0 = blockIdx.x * 64;
    const int eb = bh * Nc;
    const uint32_t sb = smem_u32(smem);
    int r0 = w * 16 + g;           // local rows r0, r0+8

    __half2 F1a = __half2half2(g_F1h[eb + i0 + r0]);
    __half2 F2a = __half2half2(g_F2h[eb + i0 + r0]);
    __half2 F1b = __half2half2(g_F1h[eb + i0 + r0 + 8]);
    __half2 F2b = __half2half2(g_F2h[eb + i0 + r0 + 8]);

    float c[8][4];
#pragma unroll
    for (int n = 0; n < 8; n++)
#pragma unroll
        for (int q = 0; q < 4; q++) c[n][q] = 0.f;
    float cz[4] = {0.f, 0.f, 0.f, 0.f};

    const char* hbase = (const char*)(g_hH + (size_t)eb * Dc);
    const char* mbase = (const char*)g_maskH;
    const uint32_t ONES = 0x3C003C00u;

    auto prefetch = [&](int ch, int buf) {
        int j0 = ch * 128;
        // h tile: 128 j-rows x 128B
#pragma unroll
        for (int q = 0; q < 8; q++) {
            int idx = tid + q * 128;
            int row = idx >> 3, cc = idx & 7;
            uint32_t dst = sb + SH_OFF + (uint32_t)buf * 16384 + (uint32_t)row * 128 +
                           (((uint32_t)cc * 16) ^ ((uint32_t)(row & 7) * 16));
            CP16(dst, hbase + ((size_t)(j0 + row) * 128 + cc * 16));
        }
        // mask tile: 64 i-rows x 256B
#pragma unroll
        for (int q = 0; q < 8; q++) {
            int idx = tid + q * 128;
            int row = idx >> 4, c16 = idx & 15;
            uint32_t dst = sb + SM_OFF + (uint32_t)buf * 16384 + (uint32_t)row * 256 +
                           (((uint32_t)c16 * 16) ^ ((uint32_t)(row & 7) * 16));
            CP16(dst, mbase + (((size_t)(i0 + row) * Nc + j0) * 2 + c16 * 16));
        }
        if (tid < 16) {
            CP16(sb + SE1_OFF + (uint32_t)buf * 256 + tid * 16, (const char*)(g_E1h + eb + j0) + tid * 16);
        } else if (tid < 32) {
            CP16(sb + SE2_OFF + (uint32_t)buf * 256 + (tid - 16) * 16, (const char*)(g_E2h + eb + j0) + (tid - 16) * 16);
        }
        CPCOMMIT();
    };

    prefetch(0, 0);

    uint32_t lmrow = (uint32_t)(lane & 15);
    uint32_t lmhi  = (uint32_t)((lane >> 4) * 16);
    uint32_t marow = (uint32_t)(w * 16) + lmrow;                  // mask row (local i)
    uint32_t maswz = (marow & 7) * 16;
    uint32_t mabase = (uint32_t)marow * 256;

    for (int ch = 0; ch < 16; ch++) {
        int buf = ch & 1;
        if (ch < 15) { prefetch(ch + 1, buf ^ 1); CPWAIT(1); }
        else         { CPWAIT(0); }
        __syncthreads();

        const __half2* e1p = (const __half2*)(smem + SE1_OFF + buf * 256);
        const __half2* e2p = (const __half2*)(smem + SE2_OFF + buf * 256);
        uint32_t sHbuf = sb + SH_OFF + (uint32_t)buf * 16384;
        uint32_t sMbuf = sb + SM_OFF + (uint32_t)buf * 16384;

        uint32_t bfr[2][16];
        // preload B for s=0
        {
            uint32_t rbase = sHbuf + lmrow * 128;
            uint32_t swz = (lmrow & 7) * 16;
#pragma unroll
            for (int p = 0; p < 4; p++) {
                uint32_t addr = rbase + (((uint32_t)(p * 32) + lmhi) ^ swz);
                asm volatile("ldmatrix.sync.aligned.m8n8.x4.trans.shared.b16 {%0,%1,%2,%3}, [%4];"
                             : "=r"(bfr[0][p*4+0]), "=r"(bfr[0][p*4+1]),
                               "=r"(bfr[0][p*4+2]), "=r"(bfr[0][p*4+3]) : "r"(addr));
            }
        }

#pragma unroll
        for (int s = 0; s < 8; s++) {
            const int cur = s & 1;
            // mask A-fragment: one ldmatrix.x4 (rows = local i, cols = 16 j)
            uint32_t m0, m1, m2, m3;
            {
                uint32_t maddr = sMbuf + mabase + (((uint32_t)(s * 32) + lmhi) ^ maswz);
                asm volatile("ldmatrix.sync.aligned.m8n8.x4.shared.b16 {%0,%1,%2,%3}, [%4];"
                             : "=r"(m0), "=r"(m1), "=r"(m2), "=r"(m3) : "r"(maddr));
            }
            __half2 e1lo = e1p[s * 8 + t],     e1hi = e1p[s * 8 + 4 + t];
            __half2 e2lo = e2p[s * 8 + t],     e2hi = e2p[s * 8 + 4 + t];

            uint32_t a0 = h2u(__hmul2(__hmax2(__hmul2(F1a, e1lo), __hmul2(F2a, e2lo)), *(__half2*)&m0));
            uint32_t a1 = h2u(__hmul2(__hmax2(__hmul2(F1b, e1lo), __hmul2(F2b, e2lo)), *(__half2*)&m1));
            uint32_t a2 = h2u(__hmul2(__hmax2(__hmul2(F1a, e1hi), __hmul2(F2a, e2hi)), *(__half2*)&m2));
            uint32_t a3 = h2u(__hmul2(__hmax2(__hmul2(F1b, e1hi), __hmul2(F2b, e2hi)), *(__half2*)&m3));

            // prefetch next step's B fragments (hide LDSM latency behind MMAs)
            if (s < 7) {
                uint32_t mrow = (uint32_t)((s + 1) * 16) + lmrow;
                uint32_t rbase = sHbuf + mrow * 128;
                uint32_t swz = (mrow & 7) * 16;
#pragma unroll
                for (int p = 0; p < 4; p++) {
                    uint32_t addr = rbase + (((uint32_t)(p * 32) + lmhi) ^ swz);
                    asm volatile("ldmatrix.sync.aligned.m8n8.x4.trans.shared.b16 {%0,%1,%2,%3}, [%4];"
                                 : "=r"(bfr[cur^1][p*4+0]), "=r"(bfr[cur^1][p*4+1]),
                                   "=r"(bfr[cur^1][p*4+2]), "=r"(bfr[cur^1][p*4+3]) : "r"(addr));
                }
            }

            asm volatile("mma.sync.aligned.m16n8k16.row.col.f32.f16.f16.f32 "
                         "{%0,%1,%2,%3}, {%4,%5,%6,%7}, {%8,%9}, {%0,%1,%2,%3};"
                         : "+f"(cz[0]), "+f"(cz[1]), "+f"(cz[2]), "+f"(cz[3])
                         : "r"(a0), "r"(a1), "r"(a2), "r"(a3), "r"(ONES), "r"(ONES));
#pragma unroll
            for (int p = 0; p < 4; p++) {
                asm volatile("mma.sync.aligned.m16n8k16.row.col.f32.f16.f16.f32 "
                             "{%0,%1,%2,%3}, {%4,%5,%6,%7}, {%8,%9}, {%0,%1,%2,%3};"
                             : "+f"(c[2*p][0]), "+f"(c[2*p][1]), "+f"(c[2*p][2]), "+f"(c[2*p][3])
                             : "r"(a0), "r"(a1), "r"(a2), "r"(a3),
                               "r"(bfr[cur][p*4+0]), "r"(bfr[cur][p*4+1]));
                asm volatile("mma.sync.aligned.m16n8k16.row.col.f32.f16.f16.f32 "
                             "{%0,%1,%2,%3}, {%4,%5,%6,%7}, {%8,%9}, {%0,%1,%2,%3};"
                             : "+f"(c[2*p+1][0]), "+f"(c[2*p+1][1]), "+f"(c[2*p+1][2]), "+f"(c[2*p+1][3])
                             : "r"(a0), "r"(a1), "r"(a2), "r"(a3),
                               "r"(bfr[cur][p*4+2]), "r"(bfr[cur][p*4+3]));
            }
        }
        __syncthreads();
    }

    float inv0 = 1.f / cz[0];
    float inv1 = 1.f / cz[2];

    int b = bh >> 2, hd = bh & 3;
    int grow = i0 + r0;
    float* d0 = out + ((size_t)(b * Nc) + grow) * (Hc * Dc) + hd * Dc + 2 * t;
    float* d1 = d0 + 8 * (Hc * Dc);
#pragma unroll
    for (int n = 0; n < 8; n++) {
        *(float2*)(d0 + n * 8) = make_float2(c[n][0] * inv0, c[n][1] * inv0);
        *(float2*)(d1 + n * 8) = make_float2(c[n][2] * inv1, c[n][3] * inv1);
    }
}

extern "C" void kernel_launch(void* const* d_in, const int* in_sizes, int n_in,
                              void* d_out, int out_size) {
    const float* x       = (const float*)d_in[0];
    const int*   adj     = (const int*)  d_in[1];
    const float* W       = (const float*)d_in[2];
    const float* att_src = (const float*)d_in[3];
    const float* att_dst = (const float*)d_in[4];
    float* out = (float*)d_out;

    cudaFuncSetAttribute(k_attn, cudaFuncAttributeMaxDynamicSharedMemorySize, SMEM_ATTN);

    k_packh<<<1024, 256>>>(adj);
    k_lin_h<<<dim3(Nc / 64, 2, Bc), 128>>>(x, W, att_src, att_dst);
    k_attn<<<dim3(Nc / 64, BHc), 128, SMEM_ATTN>>>(out);
}

// round 12
// speedup vs baseline: 1.2690x; 1.0899x over previous
#include <cuda_runtime.h>
#include <cuda_fp16.h>
#include <cstdint>

#define Bc  4
#define Nc  2048
#define INC 128
#define Hc  4
#define Dc  64
#define BHc (Bc*Hc)

// ---- scratch ----
__device__ __half   g_hH[BHc*Nc*Dc];   // h fp16 [bh][n][d]
__device__ __half   g_E1h[BHc*Nc];     // exp(v)
__device__ __half   g_E2h[BHc*Nc];     // exp(0.2 v)
__device__ __half   g_F1h[BHc*Nc];     // exp(u)
__device__ __half   g_F2h[BHc*Nc];     // exp(0.2 u)
__device__ __half   g_maskH[Nc*Nc];    // adj as fp16 {1.0, 0.0}, [i][j]

__device__ __forceinline__ uint32_t smem_u32(const void* p) {
    uint32_t a;
    asm("{ .reg .u64 t; cvta.to.shared.u64 t, %1; cvt.u32.u64 %0, t; }" : "=r"(a) : "l"(p));
    return a;
}
__device__ __forceinline__ uint32_t h2u(__half2 h) { return *(uint32_t*)&h; }

#define CP16(dst, src) asm volatile("cp.async.cg.shared.global [%0], [%1], 16;" :: "r"(dst), "l"(src))
#define CPCOMMIT()     asm volatile("cp.async.commit_group;" ::: "memory")
#define CPWAIT(n)      asm volatile("cp.async.wait_group %0;" :: "n"(n) : "memory")

// ---- adj int32 -> fp16 {1,0}, coalesced streaming convert (MLP=8) ----
// Each uint4 (4 ints) -> 1 uint2 (4 halves). Warp-task = 1024 ints -> 256 uint2.
__global__ void __launch_bounds__(256) k_packh(const int* __restrict__ adj) {
    int task = blockIdx.x * 8 + (threadIdx.x >> 5);   // 4096 warp-tasks, 1024 ints each
    int lane = threadIdx.x & 31;
    const uint4* p = (const uint4*)adj + (size_t)task * 256 + lane;
    uint2* o = (uint2*)g_maskH + (size_t)task * 256 + lane;
    uint4 v[8];
#pragma unroll
    for (int k = 0; k < 8; k++) v[k] = p[k * 32];
#pragma unroll
    for (int k = 0; k < 8; k++) {
        uint2 r;
        r.x = (((int)v[k].x > 0) ? 0x3C00u : 0u) | (((int)v[k].y > 0) ? 0x3C000000u : 0u);
        r.y = (((int)v[k].z > 0) ? 0x3C00u : 0u) | (((int)v[k].w > 0) ? 0x3C000000u : 0u);
        o[k * 32] = r;
    }
}

// ---- HMMA linear (fp32 inputs converted in staging) with fused u/v/exp epilogue ----
__global__ void __launch_bounds__(128) k_lin_h(const float* __restrict__ x,
                                               const float* __restrict__ W,
                                               const float* __restrict__ att_src,
                                               const float* __restrict__ att_dst) {
    __shared__ __align__(16) char sX[64 * 256];
    __shared__ __align__(16) char sW[128 * 256];
    int tid = threadIdx.x, w = tid >> 5, lane = tid & 31;
    int g = lane >> 2, t = lane & 3;
    int n0 = blockIdx.x * 64, cgrp = blockIdx.y, b = blockIdx.z;

    const float4* xs = (const float4*)(x + ((size_t)b * Nc + n0) * INC);
#pragma unroll
    for (int q = 0; q < 16; q++) {
        int idx = tid + q * 128;
        int row = idx >> 5, u8 = idx & 31;
        float4 v = xs[idx];
        uint2 pk;
        __half2 p0 = __floats2half2_rn(v.x, v.y), p1 = __floats2half2_rn(v.z, v.w);
        pk.x = h2u(p0); pk.y = h2u(p1);
        *(uint2*)&sX[row * 256 + ((((u8 >> 1) * 16) ^ ((row & 7) * 16)) + (u8 & 1) * 8)] = pk;
    }
    const float4* ws = (const float4*)(W + (size_t)cgrp * 128 * INC);
#pragma unroll
    for (int q = 0; q < 32; q++) {
        int idx = tid + q * 128;
        int row = idx >> 5, u8 = idx & 31;
        float4 v = ws[idx];
        uint2 pk;
        __half2 p0 = __floats2half2_rn(v.x, v.y), p1 = __floats2half2_rn(v.z, v.w);
        pk.x = h2u(p0); pk.y = h2u(p1);
        *(uint2*)&sW[row * 256 + ((((u8 >> 1) * 16) ^ ((row & 7) * 16)) + (u8 & 1) * 8)] = pk;
    }
    __syncthreads();

    float c[16][4];
#pragma unroll
    for (int n = 0; n < 16; n++)
#pragma unroll
        for (int q = 0; q < 4; q++) c[n][q] = 0.f;

    uint32_t sXb = smem_u32(sX), sWb = smem_u32(sW);
    int arow = w * 16 + (lane & 15);
    uint32_t abase = sXb + (uint32_t)arow * 256;
    uint32_t hi16  = (uint32_t)(lane >> 4) * 16;
    uint32_t aswz  = (uint32_t)((arow & 7) * 16);
    int brow_base = (lane & 7) + ((lane >> 4) << 3);
    uint32_t bk16 = (uint32_t)(((lane >> 3) & 1) * 16);

#pragma unroll
    for (int ks = 0; ks < 8; ks++) {
        uint32_t a0, a1, a2, a3;
        uint32_t aaddr = abase + (((uint32_t)(ks * 32) + hi16) ^ aswz);
        asm volatile("ldmatrix.sync.aligned.m8n8.x4.shared.b16 {%0,%1,%2,%3}, [%4];"
                     : "=r"(a0), "=r"(a1), "=r"(a2), "=r"(a3) : "r"(aaddr));
#pragma unroll
        for (int p = 0; p < 8; p++) {
            int brow = p * 16 + brow_base;
            uint32_t baddr = sWb + (uint32_t)brow * 256 +
                             (((uint32_t)(ks * 32) + bk16) ^ ((uint32_t)((brow & 7) * 16)));
            uint32_t b0, b1, b2, b3;
            asm volatile("ldmatrix.sync.aligned.m8n8.x4.shared.b16 {%0,%1,%2,%3}, [%4];"
                         : "=r"(b0), "=r"(b1), "=r"(b2), "=r"(b3) : "r"(baddr));
            asm volatile("mma.sync.aligned.m16n8k16.row.col.f32.f16.f16.f32 "
                         "{%0,%1,%2,%3}, {%4,%5,%6,%7}, {%8,%9}, {%0,%1,%2,%3};"
                         : "+f"(c[2*p][0]), "+f"(c[2*p][1]), "+f"(c[2*p][2]), "+f"(c[2*p][3])
                         : "r"(a0), "r"(a1), "r"(a2), "r"(a3), "r"(b0), "r"(b1));
            asm volatile("mma.sync.aligned.m16n8k16.row.col.f32.f16.f16.f32 "
                         "{%0,%1,%2,%3}, {%4,%5,%6,%7}, {%8,%9}, {%0,%1,%2,%3};"
                         : "+f"(c[2*p+1][0]), "+f"(c[2*p+1][1]), "+f"(c[2*p+1][2]), "+f"(c[2*p+1][3])
                         : "r"(a0), "r"(a1), "r"(a2), "r"(a3), "r"(b2), "r"(b3));
        }
    }

    float up[2][2] = {{0.f,0.f},{0.f,0.f}}, vp[2][2] = {{0.f,0.f},{0.f,0.f}};
    int row0 = w * 16 + g;
#pragma unroll
    for (int n = 0; n < 16; n++) {
        int hl = n >> 3;
        int head = cgrp * 2 + hl;
        int d = (n & 7) * 8 + 2 * t;
        float2 as2 = __ldg((const float2*)(att_src + head * 64 + d));
        float2 ad2 = __ldg((const float2*)(att_dst + head * 64 + d));
        up[0][hl] += c[n][0]*as2.x + c[n][1]*as2.y;
        vp[0][hl] += c[n][0]*ad2.x + c[n][1]*ad2.y;
        up[1][hl] += c[n][2]*as2.x + c[n][3]*as2.y;
        vp[1][hl] += c[n][2]*ad2.x + c[n][3]*ad2.y;
        __half2 h0 = __floats2half2_rn(c[n][0], c[n][1]);
        __half2 h1 = __floats2half2_rn(c[n][2], c[n][3]);
        size_t base = ((size_t)(b * Hc + head) * Nc + n0 + row0) * Dc + d;
        *(uint32_t*)&g_hH[base]          = h2u(h0);
        *(uint32_t*)&g_hH[base + 8 * Dc] = h2u(h1);
    }
#pragma unroll
    for (int rh = 0; rh < 2; rh++)
#pragma unroll
        for (int hl = 0; hl < 2; hl++) {
            up[rh][hl] += __shfl_xor_sync(0xffffffffu, up[rh][hl], 1);
            up[rh][hl] += __shfl_xor_sync(0xffffffffu, up[rh][hl], 2);
            vp[rh][hl] += __shfl_xor_sync(0xffffffffu, vp[rh][hl], 1);
            vp[rh][hl] += __shfl_xor_sync(0xffffffffu, vp[rh][hl], 2);
        }
    if (t == 0) {
#pragma unroll
        for (int rh = 0; rh < 2; rh++)
#pragma unroll
            for (int hl = 0; hl < 2; hl++) {
                int head = cgrp * 2 + hl;
                int idx = (b * Hc + head) * Nc + n0 + row0 + rh * 8;
                float u = up[rh][hl], v = vp[rh][hl];
                g_F1h[idx] = __float2half_rn(expf(u));
                g_F2h[idx] = __float2half_rn(expf(0.2f * u));
                g_E1h[idx] = __float2half_rn(expf(v));
                g_E2h[idx] = __float2half_rn(expf(0.2f * v));
            }
    }
}

// smem layout (dynamic)
#define SH_OFF   0          // 2 x 16384: h tile fp16 [j][d]
#define SM_OFF   32768      // 2 x 32768: mask tile fp16 [i-row(128)][j(128)]
#define SE1_OFF  98304      // 2 x 256
#define SE2_OFF  98816      // 2 x 256
#define SMEM_ATTN 99328

// ---- flash-GAT: 128-row i-tile, warp = 32 rows (2 m16 tiles sharing B frags) ----
__global__ void __launch_bounds__(128, 2) k_attn(float* __restrict__ out) {
    extern __shared__ __align__(16) char smem[];
    int tid = threadIdx.x;
    int w = tid >> 5, lane = tid & 31;
    int g = lane >> 2, t = lane & 3;
    int bh = blockIdx.y;
    int i0 = blockIdx.x * 128;
    const int eb = bh * Nc;
    const uint32_t sb = smem_u32(smem);
    int r0 = w * 32 + g;            // tile tl rows: r0 + tl*16 (+8)

    __half2 F1t[2][2], F2t[2][2];
#pragma unroll
    for (int tl = 0; tl < 2; tl++)
#pragma unroll
        for (int rh = 0; rh < 2; rh++) {
            int row = eb + i0 + r0 + tl * 16 + rh * 8;
            F1t[tl][rh] = __half2half2(g_F1h[row]);
            F2t[tl][rh] = __half2half2(g_F2h[row]);
        }

    float c[2][8][4];
#pragma unroll
    for (int tl = 0; tl < 2; tl++)
#pragma unroll
        for (int n = 0; n < 8; n++)
#pragma unroll
            for (int q = 0; q < 4; q++) c[tl][n][q] = 0.f;
    float cz[2][4] = {{0.f,0.f,0.f,0.f},{0.f,0.f,0.f,0.f}};

    const char* hbase = (const char*)(g_hH + (size_t)eb * Dc);
    const char* mbase = (const char*)g_maskH;
    const uint32_t ONES = 0x3C003C00u;

    auto prefetch = [&](int ch, int buf) {
        int j0 = ch * 128;
        // h tile: 128 j-rows x 128B
#pragma unroll
        for (int q = 0; q < 8; q++) {
            int idx = tid + q * 128;
            int row = idx >> 3, cc = idx & 7;
            uint32_t dst = sb + SH_OFF + (uint32_t)buf * 16384 + (uint32_t)row * 128 +
                           (((uint32_t)cc * 16) ^ ((uint32_t)(row & 7) * 16));
            CP16(dst, hbase + ((size_t)(j0 + row) * 128 + cc * 16));
        }
        // mask tile: 128 i-rows x 256B
#pragma unroll
        for (int q = 0; q < 16; q++) {
            int idx = tid + q * 128;
            int row = idx >> 4, c16 = idx & 15;
            uint32_t dst = sb + SM_OFF + (uint32_t)buf * 32768 + (uint32_t)row * 256 +
                           (((uint32_t)c16 * 16) ^ ((uint32_t)(row & 7) * 16));
            CP16(dst, mbase + (((size_t)(i0 + row) * Nc + j0) * 2 + c16 * 16));
        }
        if (tid < 16) {
            CP16(sb + SE1_OFF + (uint32_t)buf * 256 + tid * 16, (const char*)(g_E1h + eb + j0) + tid * 16);
        } else if (tid < 32) {
            CP16(sb + SE2_OFF + (uint32_t)buf * 256 + (tid - 16) * 16, (const char*)(g_E2h + eb + j0) + (tid - 16) * 16);
        }
        CPCOMMIT();
    };

    prefetch(0, 0);

    uint32_t lmrow = (uint32_t)(lane & 15);
    uint32_t lmhi  = (uint32_t)((lane >> 4) * 16);
    uint32_t maswz = (lmrow & 7) * 16;
    uint32_t mabase0 = (uint32_t)(w * 32) + lmrow;       // tl=0 mask row
    uint32_t mabase1 = mabase0 + 16;                     // tl=1 mask row

    for (int ch = 0; ch < 16; ch++) {
        int buf = ch & 1;
        if (ch < 15) { prefetch(ch + 1, buf ^ 1); CPWAIT(1); }
        else         { CPWAIT(0); }
        __syncthreads();

        const __half2* e1p = (const __half2*)(smem + SE1_OFF + buf * 256);
        const __half2* e2p = (const __half2*)(smem + SE2_OFF + buf * 256);
        uint32_t sHbuf = sb + SH_OFF + (uint32_t)buf * 16384;
        uint32_t sMbuf = sb + SM_OFF + (uint32_t)buf * 32768;

        uint32_t bfr[2][16];
        // preload B for s=0
        {
            uint32_t rbase = sHbuf + lmrow * 128;
            uint32_t swz = (lmrow & 7) * 16;
#pragma unroll
            for (int p = 0; p < 4; p++) {
                uint32_t addr = rbase + (((uint32_t)(p * 32) + lmhi) ^ swz);
                asm volatile("ldmatrix.sync.aligned.m8n8.x4.trans.shared.b16 {%0,%1,%2,%3}, [%4];"
                             : "=r"(bfr[0][p*4+0]), "=r"(bfr[0][p*4+1]),
                               "=r"(bfr[0][p*4+2]), "=r"(bfr[0][p*4+3]) : "r"(addr));
            }
        }

#pragma unroll
        for (int s = 0; s < 8; s++) {
            const int cur = s & 1;
            __half2 e1lo = e1p[s * 8 + t],     e1hi = e1p[s * 8 + 4 + t];
            __half2 e2lo = e2p[s * 8 + t],     e2hi = e2p[s * 8 + 4 + t];
            uint32_t scol = (uint32_t)(s * 32) + lmhi;

            uint32_t afr[2][4];
#pragma unroll
            for (int tl = 0; tl < 2; tl++) {
                uint32_t m0, m1, m2, m3;
                uint32_t mrow = (tl ? mabase1 : mabase0);
                uint32_t maddr = sMbuf + mrow * 256 + (scol ^ maswz);
                asm volatile("ldmatrix.sync.aligned.m8n8.x4.shared.b16 {%0,%1,%2,%3}, [%4];"
                             : "=r"(m0), "=r"(m1), "=r"(m2), "=r"(m3) : "r"(maddr));
                afr[tl][0] = h2u(__hmul2(__hmax2(__hmul2(F1t[tl][0], e1lo), __hmul2(F2t[tl][0], e2lo)), *(__half2*)&m0));
                afr[tl][1] = h2u(__hmul2(__hmax2(__hmul2(F1t[tl][1], e1lo), __hmul2(F2t[tl][1], e2lo)), *(__half2*)&m1));
                afr[tl][2] = h2u(__hmul2(__hmax2(__hmul2(F1t[tl][0], e1hi), __hmul2(F2t[tl][0], e2hi)), *(__half2*)&m2));
                afr[tl][3] = h2u(__hmul2(__hmax2(__hmul2(F1t[tl][1], e1hi), __hmul2(F2t[tl][1], e2hi)), *(__half2*)&m3));
            }

            // prefetch next step's B fragments (hide LDSM latency behind MMAs)
            if (s < 7) {
                uint32_t mrow = (uint32_t)((s + 1) * 16) + lmrow;
                uint32_t rbase = sHbuf + mrow * 128;
                uint32_t swz = (mrow & 7) * 16;
#pragma unroll
                for (int p = 0; p < 4; p++) {
                    uint32_t addr = rbase + (((uint32_t)(p * 32) + lmhi) ^ swz);
                    asm volatile("ldmatrix.sync.aligned.m8n8.x4.trans.shared.b16 {%0,%1,%2,%3}, [%4];"
                                 : "=r"(bfr[cur^1][p*4+0]), "=r"(bfr[cur^1][p*4+1]),
                                   "=r"(bfr[cur^1][p*4+2]), "=r"(bfr[cur^1][p*4+3]) : "r"(addr));
                }
            }

#pragma unroll
            for (int tl = 0; tl < 2; tl++)
                asm volatile("mma.sync.aligned.m16n8k16.row.col.f32.f16.f16.f32 "
                             "{%0,%1,%2,%3}, {%4,%5,%6,%7}, {%8,%9}, {%0,%1,%2,%3};"
                             : "+f"(cz[tl][0]), "+f"(cz[tl][1]), "+f"(cz[tl][2]), "+f"(cz[tl][3])
                             : "r"(afr[tl][0]), "r"(afr[tl][1]), "r"(afr[tl][2]), "r"(afr[tl][3]),
                               "r"(ONES), "r"(ONES));
#pragma unroll
            for (int p = 0; p < 4; p++) {
#pragma unroll
                for (int tl = 0; tl < 2; tl++) {
                    asm volatile("mma.sync.aligned.m16n8k16.row.col.f32.f16.f16.f32 "
                                 "{%0,%1,%2,%3}, {%4,%5,%6,%7}, {%8,%9}, {%0,%1,%2,%3};"
                                 : "+f"(c[tl][2*p][0]), "+f"(c[tl][2*p][1]), "+f"(c[tl][2*p][2]), "+f"(c[tl][2*p][3])
                                 : "r"(afr[tl][0]), "r"(afr[tl][1]), "r"(afr[tl][2]), "r"(afr[tl][3]),
                                   "r"(bfr[cur][p*4+0]), "r"(bfr[cur][p*4+1]));
                    asm volatile("mma.sync.aligned.m16n8k16.row.col.f32.f16.f16.f32 "
                                 "{%0,%1,%2,%3}, {%4,%5,%6,%7}, {%8,%9}, {%0,%1,%2,%3};"
                                 : "+f"(c[tl][2*p+1][0]), "+f"(c[tl][2*p+1][1]), "+f"(c[tl][2*p+1][2]), "+f"(c[tl][2*p+1][3])
                                 : "r"(afr[tl][0]), "r"(afr[tl][1]), "r"(afr[tl][2]), "r"(afr[tl][3]),
                                   "r"(bfr[cur][p*4+2]), "r"(bfr[cur][p*4+3]));
                }
            }
        }
        __syncthreads();
    }

    int b = bh >> 2, hd = bh & 3;
#pragma unroll
    for (int tl = 0; tl < 2; tl++) {
        float inv0 = 1.f / cz[tl][0];
        float inv1 = 1.f / cz[tl][2];
        int grow = i0 + r0 + tl * 16;
        float* d0 = out + ((size_t)(b * Nc) + grow) * (Hc * Dc) + hd * Dc + 2 * t;
        float* d1 = d0 + 8 * (Hc * Dc);
#pragma unroll
        for (int n = 0; n < 8; n++) {
            *(float2*)(d0 + n * 8) = make_float2(c[tl][n][0] * inv0, c[tl][n][1] * inv0);
            *(float2*)(d1 + n * 8) = make_float2(c[tl][n][2] * inv1, c[tl][n][3] * inv1);
        }
    }
}

extern "C" void kernel_launch(void* const* d_in, const int* in_sizes, int n_in,
                              void* d_out, int out_size) {
    const float* x       = (const float*)d_in[0];
    const int*   adj     = (const int*)  d_in[1];
    const float* W       = (const float*)d_in[2];
    const float* att_src = (const float*)d_in[3];
    const float* att_dst = (const float*)d_in[4];
    float* out = (float*)d_out;

    cudaFuncSetAttribute(k_attn, cudaFuncAttributeMaxDynamicSharedMemorySize, SMEM_ATTN);

    k_packh<<<512, 256>>>(adj);
    k_lin_h<<<dim3(Nc / 64, 2, Bc), 128>>>(x, W, att_src, att_dst);
    k_attn<<<dim3(Nc / 128, BHc), 128, SMEM_ATTN>>>(out);
}